// round 1
// baseline (speedup 1.0000x reference)
#include <cuda_runtime.h>
#include <math.h>

#define DIMC 2560
#define BB 2
#define SS 2048
#define SCC 512
#define HH 20
#define HDD 128
#define FFNN 10240
#define EPSF 1e-6f
#define ROWS (BB*SS)      /* 4096 */
#define ROWSC (BB*SCC)    /* 1024 */

// ---------------- scratch (device globals; no cudaMalloc allowed) ----------
__device__ float g_x   [ROWS * DIMC];
__device__ float g_qkv [ROWS * 3 * DIMC];
__device__ float g_q   [ROWS * DIMC];
__device__ float g_k   [ROWS * DIMC];
__device__ float g_attn[ROWS * DIMC];
__device__ float g_h   [ROWS * DIMC];
__device__ float g_kv  [ROWSC * 2 * DIMC];
__device__ float g_ff  [ROWS * FFNN];

// ---------------- LayerNorm (plain / gamma-beta / adaLN-modulated) ---------
__global__ __launch_bounds__(256) void ln_kernel(
    const float* __restrict__ x, float* __restrict__ out,
    const float* __restrict__ gamma, const float* __restrict__ beta,
    const float* __restrict__ sst, const float* __restrict__ temb,
    int shift_idx, int scale_idx, int S)
{
    int row = blockIdx.x;
    int b = row / S;
    const float* xr = x + (size_t)row * DIMC;
    float vals[10];
    float s1 = 0.f, s2 = 0.f;
#pragma unroll
    for (int i = 0; i < 10; ++i) {
        float v = xr[threadIdx.x + i * 256];
        vals[i] = v; s1 += v; s2 += v * v;
    }
#pragma unroll
    for (int o = 16; o > 0; o >>= 1) {
        s1 += __shfl_xor_sync(0xffffffffu, s1, o);
        s2 += __shfl_xor_sync(0xffffffffu, s2, o);
    }
    __shared__ float red[16];
    int wid = threadIdx.x >> 5;
    if ((threadIdx.x & 31) == 0) { red[wid] = s1; red[8 + wid] = s2; }
    __syncthreads();
    float ts = 0.f, tq = 0.f;
#pragma unroll
    for (int i = 0; i < 8; ++i) { ts += red[i]; tq += red[8 + i]; }
    float mean = ts * (1.f / DIMC);
    float var  = tq * (1.f / DIMC) - mean * mean;
    float inv  = rsqrtf(var + EPSF);
    float* orow = out + (size_t)row * DIMC;
#pragma unroll
    for (int i = 0; i < 10; ++i) {
        int c = threadIdx.x + i * 256;
        float y = (vals[i] - mean) * inv;
        if (sst) {
            float scv = sst[scale_idx * DIMC + c] + temb[((size_t)b * 6 + scale_idx) * DIMC + c];
            float shv = sst[shift_idx * DIMC + c] + temb[((size_t)b * 6 + shift_idx) * DIMC + c];
            y = y * (1.f + scv) + shv;
        } else if (gamma) {
            y = y * gamma[c] + beta[c];
        }
        orow[c] = y;
    }
}

// ---------------- RMSNorm (+ optional RoPE) --------------------------------
__global__ __launch_bounds__(256) void rmsrope_kernel(
    const float* __restrict__ in, int istride, int ioff,
    float* __restrict__ out, const float* __restrict__ w,
    const float* __restrict__ cosT, const float* __restrict__ sinT, int S)
{
    int row = blockIdx.x;
    int s = row % S;
    const float* xr = in + (size_t)row * istride + ioff;
    float vals[10];
    float sq = 0.f;
#pragma unroll
    for (int i = 0; i < 10; ++i) {
        float v = xr[threadIdx.x + i * 256];
        vals[i] = v; sq += v * v;
    }
#pragma unroll
    for (int o = 16; o > 0; o >>= 1) sq += __shfl_xor_sync(0xffffffffu, sq, o);
    __shared__ float red[8];
    int wid = threadIdx.x >> 5;
    if ((threadIdx.x & 31) == 0) red[wid] = sq;
    __syncthreads();
    float tq = 0.f;
#pragma unroll
    for (int i = 0; i < 8; ++i) tq += red[i];
    float inv = rsqrtf(tq * (1.f / DIMC) + EPSF);
    float* orow = out + (size_t)row * DIMC;
#pragma unroll
    for (int i = 0; i < 10; ++i) {
        int c = threadIdx.x + i * 256;
        int d = c & (HDD - 1);
        int pc = (d < 64) ? c + 64 : c - 64;
        float y  = vals[i] * inv * w[c];
        float py = xr[pc]  * inv * w[pc];
        float cv = cosT[(size_t)s * HDD + d];
        float sv = sinT[(size_t)s * HDD + d];
        orow[c] = y * cv + ((d < 64) ? -py : py) * sv;
    }
}

__global__ __launch_bounds__(256) void rms_kernel(
    float* data, int stride, int off, const float* __restrict__ w)
{
    int row = blockIdx.x;
    float* xr = data + (size_t)row * stride + off;
    float vals[10];
    float sq = 0.f;
#pragma unroll
    for (int i = 0; i < 10; ++i) {
        float v = xr[threadIdx.x + i * 256];
        vals[i] = v; sq += v * v;
    }
#pragma unroll
    for (int o = 16; o > 0; o >>= 1) sq += __shfl_xor_sync(0xffffffffu, sq, o);
    __shared__ float red[8];
    int wid = threadIdx.x >> 5;
    if ((threadIdx.x & 31) == 0) red[wid] = sq;
    __syncthreads();
    float tq = 0.f;
#pragma unroll
    for (int i = 0; i < 8; ++i) tq += red[i];
    float inv = rsqrtf(tq * (1.f / DIMC) + EPSF);
#pragma unroll
    for (int i = 0; i < 10; ++i) {
        int c = threadIdx.x + i * 256;
        xr[c] = vals[i] * inv * w[c];
    }
}

// ---------------- tiled NT GEMM: C[M,N] = A[M,K] @ W[N,K]^T + bias ---------
// epilogue modes: 0 plain, 1 +res, 2 res + gate*(..), 3 gelu(tanh)
#define GBM 128
#define GBN 128
#define GBK 8

__global__ __launch_bounds__(256) void gemm_nt(
    const float* __restrict__ A, const float* __restrict__ W,
    const float* __restrict__ bias, float* C,
    int M, int N, int K, int mode,
    const float* res, const float* __restrict__ sst,
    const float* __restrict__ temb, int gate_idx, int rows_per_batch)
{
    __shared__ float As[GBK][GBM + 4];
    __shared__ float Ws[GBK][GBN + 4];
    int bx = blockIdx.x, by = blockIdx.y;
    int tid = threadIdx.x;
    int tx = tid & 15, ty = tid >> 4;
    const float* Ab = A + (size_t)by * GBM * K;
    const float* Wb = W + (size_t)bx * GBN * K;
    int lr = tid >> 1;
    int lc = (tid & 1) * 4;

    float acc[8][8];
#pragma unroll
    for (int i = 0; i < 8; ++i)
#pragma unroll
        for (int j = 0; j < 8; ++j) acc[i][j] = 0.f;

    float4 a4 = *(const float4*)(Ab + (size_t)lr * K + lc);
    float4 w4 = *(const float4*)(Wb + (size_t)lr * K + lc);

    for (int k0 = 0; k0 < K; k0 += GBK) {
        __syncthreads();
        As[lc + 0][lr] = a4.x; As[lc + 1][lr] = a4.y; As[lc + 2][lr] = a4.z; As[lc + 3][lr] = a4.w;
        Ws[lc + 0][lr] = w4.x; Ws[lc + 1][lr] = w4.y; Ws[lc + 2][lr] = w4.z; Ws[lc + 3][lr] = w4.w;
        __syncthreads();
        if (k0 + GBK < K) {
            a4 = *(const float4*)(Ab + (size_t)lr * K + k0 + GBK + lc);
            w4 = *(const float4*)(Wb + (size_t)lr * K + k0 + GBK + lc);
        }
#pragma unroll
        for (int kk = 0; kk < GBK; ++kk) {
            float4 a0 = *(const float4*)&As[kk][ty * 8];
            float4 a1 = *(const float4*)&As[kk][ty * 8 + 4];
            float4 b0 = *(const float4*)&Ws[kk][tx * 8];
            float4 b1 = *(const float4*)&Ws[kk][tx * 8 + 4];
            float av[8] = {a0.x, a0.y, a0.z, a0.w, a1.x, a1.y, a1.z, a1.w};
            float bv[8] = {b0.x, b0.y, b0.z, b0.w, b1.x, b1.y, b1.z, b1.w};
#pragma unroll
            for (int i = 0; i < 8; ++i)
#pragma unroll
                for (int j = 0; j < 8; ++j) acc[i][j] += av[i] * bv[j];
        }
    }

    int mbase = by * GBM + ty * 8;
    int nbase = bx * GBN + tx * 8;
#pragma unroll
    for (int i = 0; i < 8; ++i) {
        int mm = mbase + i;
        size_t rowb = (size_t)mm * N;
#pragma unroll
        for (int j = 0; j < 8; ++j) {
            int nn = nbase + j;
            float v = acc[i][j] + bias[nn];
            if (mode == 1) {
                v += res[rowb + nn];
            } else if (mode == 2) {
                int bb = mm / rows_per_batch;
                float gt = sst[(size_t)gate_idx * N + nn] + temb[((size_t)bb * 6 + gate_idx) * N + nn];
                v = res[rowb + nn] + gt * v;
            } else if (mode == 3) {
                float u = v;
                v = 0.5f * u * (1.f + tanhf(0.7978845608028654f * (u + 0.044715f * u * u * u)));
            }
            C[rowb + nn] = v;
        }
    }
}

// ---------------- flash attention (online softmax) -------------------------
// grid: (S/64, H, B); block 256. out layout (B,S,DIM): merge-heads is free.
#define AT_PAD 132
#define ATT_SMEM ((3 * 64 * AT_PAD + 64 * 65) * (int)sizeof(float))

__global__ __launch_bounds__(256) void attn_kernel(
    const float* __restrict__ q, int qstride,
    const float* __restrict__ k, int kstride, int koff,
    const float* __restrict__ v, int vstride, int voff,
    float* __restrict__ out, int ostride,
    int S, int Skv, float scale)
{
    extern __shared__ float smp[];
    float* qsm = smp;
    float* ksm = qsm + 64 * AT_PAD;
    float* vsm = ksm + 64 * AT_PAD;
    float* sc  = vsm + 64 * AT_PAD;

    int s0 = blockIdx.x * 64;
    int h  = blockIdx.y;
    int b  = blockIdx.z;
    int tid = threadIdx.x;

    // load Q tile (pre-scaled)
    for (int f = tid; f < 64 * 32; f += 256) {
        int r = f >> 5, d4 = f & 31;
        float4 qv = *(const float4*)(q + ((size_t)(b * S + s0 + r)) * qstride + h * HDD + d4 * 4);
        qv.x *= scale; qv.y *= scale; qv.z *= scale; qv.w *= scale;
        *(float4*)(qsm + r * AT_PAD + d4 * 4) = qv;
    }

    int qr = tid & 63;
    int quarter = tid >> 6;
    int c0 = quarter * 16;

    float o[32];
#pragma unroll
    for (int j = 0; j < 32; ++j) o[j] = 0.f;
    float m = -1e30f, l = 0.f;

    for (int kt = 0; kt < Skv; kt += 64) {
        __syncthreads();   // prior consumers done (and Q tile visible on iter 0)
        for (int f = tid; f < 64 * 32; f += 256) {
            int r = f >> 5, d4 = f & 31;
            size_t krow = (size_t)(b * Skv + kt + r);
            float4 kvv = *(const float4*)(k + krow * kstride + koff + h * HDD + d4 * 4);
            *(float4*)(ksm + r * AT_PAD + d4 * 4) = kvv;
            float4 vvv = *(const float4*)(v + krow * vstride + voff + h * HDD + d4 * 4);
            *(float4*)(vsm + r * AT_PAD + d4 * 4) = vvv;
        }
        __syncthreads();

        // scores: this thread computes sc[qr][c0..c0+15]
        float accs[16];
#pragma unroll
        for (int c = 0; c < 16; ++c) accs[c] = 0.f;
        for (int d4 = 0; d4 < 32; ++d4) {
            float4 qv = *(const float4*)(qsm + qr * AT_PAD + d4 * 4);
#pragma unroll
            for (int c = 0; c < 16; ++c) {
                float4 kv4 = *(const float4*)(ksm + (c0 + c) * AT_PAD + d4 * 4);
                accs[c] += qv.x * kv4.x + qv.y * kv4.y + qv.z * kv4.z + qv.w * kv4.w;
            }
        }
#pragma unroll
        for (int c = 0; c < 16; ++c) sc[qr * 65 + c0 + c] = accs[c];
        __syncthreads();

        // online softmax + PV for row qr, dims [quarter*32, quarter*32+32)
        float tmax = -1e30f;
        for (int c = 0; c < 64; ++c) tmax = fmaxf(tmax, sc[qr * 65 + c]);
        float mnew = fmaxf(m, tmax);
        float corr = __expf(m - mnew);
        l *= corr;
#pragma unroll
        for (int j = 0; j < 32; ++j) o[j] *= corr;
        for (int c = 0; c < 64; ++c) {
            float p = __expf(sc[qr * 65 + c] - mnew);
            l += p;
            const float* vr = vsm + c * AT_PAD + quarter * 32;
#pragma unroll
            for (int j4 = 0; j4 < 8; ++j4) {
                float4 vv = *(const float4*)(vr + j4 * 4);
                o[j4 * 4 + 0] += p * vv.x;
                o[j4 * 4 + 1] += p * vv.y;
                o[j4 * 4 + 2] += p * vv.z;
                o[j4 * 4 + 3] += p * vv.w;
            }
        }
        m = mnew;
    }

    float invl = 1.f / l;
    float* orow = out + ((size_t)(b * S + s0 + qr)) * ostride + h * HDD + quarter * 32;
#pragma unroll
    for (int j4 = 0; j4 < 8; ++j4) {
        float4 vv;
        vv.x = o[j4 * 4 + 0] * invl;
        vv.y = o[j4 * 4 + 1] * invl;
        vv.z = o[j4 * 4 + 2] * invl;
        vv.w = o[j4 * 4 + 3] * invl;
        *(float4*)(orow + j4 * 4) = vv;
    }
}

// ---------------- host orchestration ---------------------------------------
extern "C" void kernel_launch(void* const* d_in, const int* in_sizes, int n_in,
                              void* d_out, int out_size)
{
    const float* hs    = (const float*)d_in[0];
    const float* enc   = (const float*)d_in[1];
    const float* temb  = (const float*)d_in[2];
    const float* cosT  = (const float*)d_in[3];
    const float* sinT  = (const float*)d_in[4];
    const float* sst   = (const float*)d_in[5];
    const float* w_qkv = (const float*)d_in[6];
    const float* b_qkv = (const float*)d_in[7];
    const float* rms_q1= (const float*)d_in[8];
    const float* rms_k1= (const float*)d_in[9];
    const float* w_o1  = (const float*)d_in[10];
    const float* b_o1  = (const float*)d_in[11];
    const float* ln2_g = (const float*)d_in[12];
    const float* ln2_b = (const float*)d_in[13];
    const float* w_q2  = (const float*)d_in[14];
    const float* b_q2  = (const float*)d_in[15];
    const float* w_kv2 = (const float*)d_in[16];
    const float* b_kv2 = (const float*)d_in[17];
    const float* rms_q2= (const float*)d_in[18];
    const float* rms_k2= (const float*)d_in[19];
    const float* w_o2  = (const float*)d_in[20];
    const float* b_o2  = (const float*)d_in[21];
    const float* w_ff1 = (const float*)d_in[22];
    const float* b_ff1 = (const float*)d_in[23];
    const float* w_ff2 = (const float*)d_in[24];
    const float* b_ff2 = (const float*)d_in[25];
    float* out = (float*)d_out;

    float *px, *pqkv, *pq, *pk, *pattn, *ph, *pkv, *pff;
    cudaGetSymbolAddress((void**)&px,    g_x);
    cudaGetSymbolAddress((void**)&pqkv,  g_qkv);
    cudaGetSymbolAddress((void**)&pq,    g_q);
    cudaGetSymbolAddress((void**)&pk,    g_k);
    cudaGetSymbolAddress((void**)&pattn, g_attn);
    cudaGetSymbolAddress((void**)&ph,    g_h);
    cudaGetSymbolAddress((void**)&pkv,   g_kv);
    cudaGetSymbolAddress((void**)&pff,   g_ff);

    cudaFuncSetAttribute(attn_kernel, cudaFuncAttributeMaxDynamicSharedMemorySize, ATT_SMEM);

    const float scale = 0.08838834764831845f;  // 128^-0.5

    // 1) x = modLN(h; shift=0, scale=1)
    ln_kernel<<<ROWS, 256>>>(hs, px, nullptr, nullptr, sst, temb, 0, 1, SS);
    // 2) qkv = x @ w_qkv^T + b
    gemm_nt<<<dim3(3 * DIMC / GBN, ROWS / GBM), 256>>>(px, w_qkv, b_qkv, pqkv,
        ROWS, 3 * DIMC, DIMC, 0, nullptr, nullptr, nullptr, 0, SS);
    // 3) q,k = rope(rms(.))
    rmsrope_kernel<<<ROWS, 256>>>(pqkv, 3 * DIMC, 0,    pq, rms_q1, cosT, sinT, SS);
    rmsrope_kernel<<<ROWS, 256>>>(pqkv, 3 * DIMC, DIMC, pk, rms_k1, cosT, sinT, SS);
    // 4) self-attention (v lives inside qkv buffer)
    attn_kernel<<<dim3(SS / 64, HH, BB), 256, ATT_SMEM>>>(
        pq, DIMC, pk, DIMC, 0, pqkv, 3 * DIMC, 2 * DIMC, pattn, DIMC, SS, SS, scale);
    // 5) h = hidden + gate_sa * (attn @ w_o1^T + b_o1)
    gemm_nt<<<dim3(DIMC / GBN, ROWS / GBM), 256>>>(pattn, w_o1, b_o1, ph,
        ROWS, DIMC, DIMC, 2, hs, sst, temb, 2, SS);
    // 6) x = LN(h, g, b)
    ln_kernel<<<ROWS, 256>>>(ph, px, ln2_g, ln2_b, nullptr, nullptr, 0, 0, SS);
    // 7) q2 = rms(x @ w_q2^T + b_q2)
    gemm_nt<<<dim3(DIMC / GBN, ROWS / GBM), 256>>>(px, w_q2, b_q2, pq,
        ROWS, DIMC, DIMC, 0, nullptr, nullptr, nullptr, 0, SS);
    rms_kernel<<<ROWS, 256>>>(pq, DIMC, 0, rms_q2);
    // 8) kv = enc @ w_kv2^T + b; rms on k half (in place)
    gemm_nt<<<dim3(2 * DIMC / GBN, ROWSC / GBM), 256>>>(enc, w_kv2, b_kv2, pkv,
        ROWSC, 2 * DIMC, DIMC, 0, nullptr, nullptr, nullptr, 0, SCC);
    rms_kernel<<<ROWSC, 256>>>(pkv, 2 * DIMC, 0, rms_k2);
    // 9) cross-attention (Skv = 512)
    attn_kernel<<<dim3(SS / 64, HH, BB), 256, ATT_SMEM>>>(
        pq, DIMC, pkv, 2 * DIMC, 0, pkv, 2 * DIMC, DIMC, pattn, DIMC, SS, SCC, scale);
    // 10) h += attn @ w_o2^T + b_o2
    gemm_nt<<<dim3(DIMC / GBN, ROWS / GBM), 256>>>(pattn, w_o2, b_o2, ph,
        ROWS, DIMC, DIMC, 1, ph, nullptr, nullptr, 0, SS);
    // 11) x = modLN(h; shift=3, scale=4)
    ln_kernel<<<ROWS, 256>>>(ph, px, nullptr, nullptr, sst, temb, 3, 4, SS);
    // 12) f = gelu(x @ w_ff1^T + b_ff1)
    gemm_nt<<<dim3(FFNN / GBN, ROWS / GBM), 256>>>(px, w_ff1, b_ff1, pff,
        ROWS, FFNN, DIMC, 3, nullptr, nullptr, nullptr, 0, SS);
    // 13) out = h + gate_ff * (f @ w_ff2^T + b_ff2)
    gemm_nt<<<dim3(DIMC / GBN, ROWS / GBM), 256>>>(pff, w_ff2, b_ff2, out,
        ROWS, DIMC, FFNN, 2, ph, sst, temb, 5, SS);
}

// round 3
// speedup vs baseline: 1.5784x; 1.5784x over previous
#include <cuda_runtime.h>
#include <cuda_bf16.h>
#include <math.h>
#include <stdint.h>

#define DIMC 2560
#define BB 2
#define SS 2048
#define SCC 512
#define HH 20
#define HDD 128
#define FFNN 10240
#define EPSF 1e-6f
#define ROWS (BB*SS)      /* 4096 */
#define ROWSC (BB*SCC)    /* 1024 */

typedef __nv_bfloat16 bf16;
typedef __nv_bfloat162 bf162;

// ---------------- scratch (device globals) ----------------
__device__ float g_qkv[(size_t)ROWS*3*DIMC];
__device__ float g_q  [(size_t)ROWS*DIMC];
__device__ float g_k  [(size_t)ROWS*DIMC];
__device__ float g_h  [(size_t)ROWS*DIMC];
__device__ float g_kv [(size_t)ROWSC*2*DIMC];
__device__ bf16 g_xh[(size_t)ROWS*DIMC],  g_xl[(size_t)ROWS*DIMC];
__device__ bf16 g_ah[(size_t)ROWS*DIMC],  g_al[(size_t)ROWS*DIMC];
__device__ bf16 g_fh[(size_t)ROWS*FFNN],  g_fl[(size_t)ROWS*FFNN];
__device__ bf16 g_eh[(size_t)ROWSC*DIMC], g_el[(size_t)ROWSC*DIMC];
__device__ bf16 g_w0h[(size_t)3*DIMC*DIMC], g_w0l[(size_t)3*DIMC*DIMC];
__device__ bf16 g_w1h[(size_t)DIMC*DIMC],   g_w1l[(size_t)DIMC*DIMC];
__device__ bf16 g_w2h[(size_t)DIMC*DIMC],   g_w2l[(size_t)DIMC*DIMC];
__device__ bf16 g_w3h[(size_t)2*DIMC*DIMC], g_w3l[(size_t)2*DIMC*DIMC];
__device__ bf16 g_w4h[(size_t)DIMC*DIMC],   g_w4l[(size_t)DIMC*DIMC];
__device__ bf16 g_w5h[(size_t)FFNN*DIMC],   g_w5l[(size_t)FFNN*DIMC];
__device__ bf16 g_w6h[(size_t)DIMC*FFNN],   g_w6l[(size_t)DIMC*FFNN];

// ---------------- helpers ----------------
__device__ __forceinline__ void cp_async16(uint32_t saddr, const void* gaddr){
    asm volatile("cp.async.cg.shared.global [%0], [%1], 16;" :: "r"(saddr), "l"(gaddr));
}
__device__ __forceinline__ void cp_commit(){ asm volatile("cp.async.commit_group;" ::: "memory"); }
__device__ __forceinline__ uint32_t smem_u32(const void* p){
    uint32_t a; asm("{ .reg .u64 t; cvta.to.shared.u64 t, %1; cvt.u32.u64 %0, t; }" : "=r"(a) : "l"(p)); return a;
}
__device__ __forceinline__ void mma16816(float* d, const uint32_t* a, const uint32_t* b){
    asm volatile("mma.sync.aligned.m16n8k16.row.col.f32.bf16.bf16.f32 "
        "{%0,%1,%2,%3}, {%4,%5,%6,%7}, {%8,%9}, {%0,%1,%2,%3};"
        : "+f"(d[0]), "+f"(d[1]), "+f"(d[2]), "+f"(d[3])
        : "r"(a[0]), "r"(a[1]), "r"(a[2]), "r"(a[3]), "r"(b[0]), "r"(b[1]));
}
__device__ __forceinline__ float gelu_tanh(float u){
    return 0.5f * u * (1.f + tanhf(0.7978845608028654f * (u + 0.044715f * u * u * u)));
}

// ---------------- split fp32 -> bf16 hi/lo ----------------
__global__ __launch_bounds__(256) void split_kernel(
    const float* __restrict__ src, bf16* __restrict__ hi, bf16* __restrict__ lo, size_t n)
{
    size_t i = ((size_t)blockIdx.x * 256 + threadIdx.x) * 4;
    size_t stride = (size_t)gridDim.x * 256 * 4;
    for (; i < n; i += stride) {
        float4 v = *(const float4*)(src + i);
        bf162 h0, h1, l0, l1;
        h0.x = __float2bfloat16(v.x); h0.y = __float2bfloat16(v.y);
        h1.x = __float2bfloat16(v.z); h1.y = __float2bfloat16(v.w);
        l0.x = __float2bfloat16(v.x - __bfloat162float(h0.x));
        l0.y = __float2bfloat16(v.y - __bfloat162float(h0.y));
        l1.x = __float2bfloat16(v.z - __bfloat162float(h1.x));
        l1.y = __float2bfloat16(v.w - __bfloat162float(h1.y));
        *(bf162*)(hi + i) = h0; *(bf162*)(hi + i + 2) = h1;
        *(bf162*)(lo + i) = l0; *(bf162*)(lo + i + 2) = l1;
    }
}

// ---------------- LayerNorm -> bf16 hi/lo ----------------
__global__ __launch_bounds__(256) void ln_kernel(
    const float* __restrict__ x, bf16* __restrict__ ohi, bf16* __restrict__ olo,
    const float* __restrict__ gamma, const float* __restrict__ beta,
    const float* __restrict__ sst, const float* __restrict__ temb,
    int shift_idx, int scale_idx, int S)
{
    int row = blockIdx.x;
    int b = row / S;
    const float* xr = x + (size_t)row * DIMC;
    float vals[10];
    float s1 = 0.f, s2 = 0.f;
#pragma unroll
    for (int i = 0; i < 10; ++i) {
        float v = xr[threadIdx.x + i * 256];
        vals[i] = v; s1 += v; s2 += v * v;
    }
#pragma unroll
    for (int o = 16; o > 0; o >>= 1) {
        s1 += __shfl_xor_sync(0xffffffffu, s1, o);
        s2 += __shfl_xor_sync(0xffffffffu, s2, o);
    }
    __shared__ float red[16];
    int wid = threadIdx.x >> 5;
    if ((threadIdx.x & 31) == 0) { red[wid] = s1; red[8 + wid] = s2; }
    __syncthreads();
    float ts = 0.f, tq = 0.f;
#pragma unroll
    for (int i = 0; i < 8; ++i) { ts += red[i]; tq += red[8 + i]; }
    float mean = ts * (1.f / DIMC);
    float var  = tq * (1.f / DIMC) - mean * mean;
    float inv  = rsqrtf(var + EPSF);
    size_t ro = (size_t)row * DIMC;
#pragma unroll
    for (int i = 0; i < 10; ++i) {
        int c = threadIdx.x + i * 256;
        float y = (vals[i] - mean) * inv;
        if (sst) {
            float scv = sst[scale_idx * DIMC + c] + temb[((size_t)b * 6 + scale_idx) * DIMC + c];
            float shv = sst[shift_idx * DIMC + c] + temb[((size_t)b * 6 + shift_idx) * DIMC + c];
            y = y * (1.f + scv) + shv;
        } else if (gamma) {
            y = y * gamma[c] + beta[c];
        }
        bf16 h = __float2bfloat16(y);
        ohi[ro + c] = h;
        olo[ro + c] = __float2bfloat16(y - __bfloat162float(h));
    }
}

// ---------------- RMSNorm + RoPE (f32 out, feeds attention) ---------------
__global__ __launch_bounds__(256) void rmsrope_kernel(
    const float* __restrict__ in, int istride, int ioff,
    float* __restrict__ out, const float* __restrict__ w,
    const float* __restrict__ cosT, const float* __restrict__ sinT, int S)
{
    int row = blockIdx.x;
    int s = row % S;
    const float* xr = in + (size_t)row * istride + ioff;
    float vals[10];
    float sq = 0.f;
#pragma unroll
    for (int i = 0; i < 10; ++i) {
        float v = xr[threadIdx.x + i * 256];
        vals[i] = v; sq += v * v;
    }
#pragma unroll
    for (int o = 16; o > 0; o >>= 1) sq += __shfl_xor_sync(0xffffffffu, sq, o);
    __shared__ float red[8];
    int wid = threadIdx.x >> 5;
    if ((threadIdx.x & 31) == 0) red[wid] = sq;
    __syncthreads();
    float tq = 0.f;
#pragma unroll
    for (int i = 0; i < 8; ++i) tq += red[i];
    float inv = rsqrtf(tq * (1.f / DIMC) + EPSF);
    float* orow = out + (size_t)row * DIMC;
#pragma unroll
    for (int i = 0; i < 10; ++i) {
        int c = threadIdx.x + i * 256;
        int d = c & (HDD - 1);
        int pc = (d < 64) ? c + 64 : c - 64;
        float y  = vals[i] * inv * w[c];
        float py = xr[pc]  * inv * w[pc];
        float cv = cosT[(size_t)s * HDD + d];
        float sv = sinT[(size_t)s * HDD + d];
        orow[c] = y * cv + ((d < 64) ? -py : py) * sv;
    }
}

__global__ __launch_bounds__(256) void rms_kernel(
    float* data, int stride, int off, const float* __restrict__ w)
{
    int row = blockIdx.x;
    float* xr = data + (size_t)row * stride + off;
    float vals[10];
    float sq = 0.f;
#pragma unroll
    for (int i = 0; i < 10; ++i) {
        float v = xr[threadIdx.x + i * 256];
        vals[i] = v; sq += v * v;
    }
#pragma unroll
    for (int o = 16; o > 0; o >>= 1) sq += __shfl_xor_sync(0xffffffffu, sq, o);
    __shared__ float red[8];
    int wid = threadIdx.x >> 5;
    if ((threadIdx.x & 31) == 0) red[wid] = sq;
    __syncthreads();
    float tq = 0.f;
#pragma unroll
    for (int i = 0; i < 8; ++i) tq += red[i];
    float inv = rsqrtf(tq * (1.f / DIMC) + EPSF);
#pragma unroll
    for (int i = 0; i < 10; ++i) {
        int c = threadIdx.x + i * 256;
        xr[c] = vals[i] * inv * w[c];
    }
}

// ---------------- mma.sync split-bf16 GEMM ----------------
// C[M,N] = (Ahi+Alo)[M,K] @ (Bhi+Blo)[N,K]^T + bias; 3 terms hi*hi, lo*hi, hi*lo
// CTA tile 128x128, warp tile 64x32, K-tile 32, 4-stage cp.async pipeline.
// smem row stride 40 bf16 (80B): fragment loads are bank-conflict-free.
#define KT 32
#define GST 4
#define ARS 40                       /* bf16 elems per smem row */
#define TILEB (128 * ARS * 2)        /* 10240 bytes per operand tile */
#define STAGEB (2 * TILEB)           /* 20480 */
#define GEMM_SMEM (GST * STAGEB)     /* 81920 */

__global__ __launch_bounds__(256, 2) void gemm_mma(
    const bf16* __restrict__ Ahi, const bf16* __restrict__ Alo,
    const bf16* __restrict__ Bhi, const bf16* __restrict__ Blo,
    const float* __restrict__ bias,
    float* __restrict__ C, bf16* __restrict__ Chi, bf16* __restrict__ Clo,
    int N, int K, int mode,
    const float* __restrict__ res, const float* __restrict__ sst,
    const float* __restrict__ temb, int gate_idx, int rows_per_batch)
{
    extern __shared__ char smem[];
    const uint32_t sb = smem_u32(smem);
    const int tid = threadIdx.x;
    const int wid = tid >> 5, lane = tid & 31;
    const int wm = wid & 1, wn = wid >> 1;
    const int g = lane >> 2, tig = lane & 3;
    const int mt = blockIdx.x, nt = blockIdx.y;

    const int K32 = K >> 5;
    const int NIT = 3 * K32;
    const size_t abase = (size_t)mt * 128 * K;
    const size_t bbase = (size_t)nt * 128 * K;
    const size_t gr = (size_t)K * 2;  // global row bytes

    auto load_tile = [&](int it) {
        int seg = it / K32;
        int k0 = (it - seg * K32) << 5;
        const bf16* Asrc = (seg == 1) ? Alo : Ahi;
        const bf16* Bsrc = (seg == 2) ? Blo : Bhi;
        const char* Ag = (const char*)(Asrc + abase + k0);
        const char* Bg = (const char*)(Bsrc + bbase + k0);
        uint32_t s0 = sb + (uint32_t)(it & (GST - 1)) * STAGEB;
#pragma unroll
        for (int i = 0; i < 2; ++i) {
            int ch = i * 256 + tid;
            int r = ch >> 2, c = ch & 3;
            cp_async16(s0 + (uint32_t)(r * 80 + c * 16), Ag + (size_t)r * gr + c * 16);
        }
#pragma unroll
        for (int i = 0; i < 2; ++i) {
            int ch = i * 256 + tid;
            int r = ch >> 2, c = ch & 3;
            cp_async16(s0 + TILEB + (uint32_t)(r * 80 + c * 16), Bg + (size_t)r * gr + c * 16);
        }
        cp_commit();
    };

    load_tile(0); load_tile(1); load_tile(2);

    float acc[4][4][4];
#pragma unroll
    for (int mi = 0; mi < 4; ++mi)
#pragma unroll
        for (int ni = 0; ni < 4; ++ni)
#pragma unroll
            for (int j = 0; j < 4; ++j) acc[mi][ni][j] = 0.f;

    for (int it = 0; it < NIT; ++it) {
        asm volatile("cp.async.wait_group 2;" ::: "memory");
        __syncthreads();
        if (it + 3 < NIT) load_tile(it + 3); else cp_commit();

        const bf16* sA = (const bf16*)(smem + (size_t)(it & (GST - 1)) * STAGEB);
        const bf16* sB = (const bf16*)(smem + (size_t)(it & (GST - 1)) * STAGEB + TILEB);
#pragma unroll
        for (int ks = 0; ks < 2; ++ks) {
            int kb = ks * 16 + tig * 2;
            uint32_t afr[4][4];
#pragma unroll
            for (int mi = 0; mi < 4; ++mi) {
                int r = wm * 64 + mi * 16 + g;
                afr[mi][0] = *(const uint32_t*)(sA + r * ARS + kb);
                afr[mi][1] = *(const uint32_t*)(sA + (r + 8) * ARS + kb);
                afr[mi][2] = *(const uint32_t*)(sA + r * ARS + kb + 8);
                afr[mi][3] = *(const uint32_t*)(sA + (r + 8) * ARS + kb + 8);
            }
            uint32_t bfr[4][2];
#pragma unroll
            for (int ni = 0; ni < 4; ++ni) {
                int nr = wn * 32 + ni * 8 + g;
                bfr[ni][0] = *(const uint32_t*)(sB + nr * ARS + kb);
                bfr[ni][1] = *(const uint32_t*)(sB + nr * ARS + kb + 8);
            }
#pragma unroll
            for (int mi = 0; mi < 4; ++mi)
#pragma unroll
                for (int ni = 0; ni < 4; ++ni)
                    mma16816(acc[mi][ni], afr[mi], bfr[ni]);
        }
    }

    // ---- epilogue ----
#pragma unroll
    for (int mi = 0; mi < 4; ++mi) {
#pragma unroll
        for (int half = 0; half < 2; ++half) {
            int m = mt * 128 + wm * 64 + mi * 16 + g + half * 8;
            size_t rowb = (size_t)m * N;
#pragma unroll
            for (int ni = 0; ni < 4; ++ni) {
                int n = nt * 128 + wn * 32 + ni * 8 + tig * 2;
                float v0 = acc[mi][ni][half * 2 + 0] + bias[n];
                float v1 = acc[mi][ni][half * 2 + 1] + bias[n + 1];
                if (mode == 3) {
                    float u0 = gelu_tanh(v0), u1 = gelu_tanh(v1);
                    bf16 h0 = __float2bfloat16(u0), h1 = __float2bfloat16(u1);
                    bf162 hv; hv.x = h0; hv.y = h1;
                    bf162 lv;
                    lv.x = __float2bfloat16(u0 - __bfloat162float(h0));
                    lv.y = __float2bfloat16(u1 - __bfloat162float(h1));
                    *(bf162*)(Chi + rowb + n) = hv;
                    *(bf162*)(Clo + rowb + n) = lv;
                } else if (mode == 2) {
                    int bb = m / rows_per_batch;
                    float g0 = sst[(size_t)gate_idx * N + n]     + temb[((size_t)bb * 6 + gate_idx) * N + n];
                    float g1 = sst[(size_t)gate_idx * N + n + 1] + temb[((size_t)bb * 6 + gate_idx) * N + n + 1];
                    float2 rv = *(const float2*)(res + rowb + n);
                    float2 w; w.x = rv.x + g0 * v0; w.y = rv.y + g1 * v1;
                    *(float2*)(C + rowb + n) = w;
                } else if (mode == 1) {
                    float2 rv = *(const float2*)(res + rowb + n);
                    float2 w; w.x = rv.x + v0; w.y = rv.y + v1;
                    *(float2*)(C + rowb + n) = w;
                } else {
                    float2 w; w.x = v0; w.y = v1;
                    *(float2*)(C + rowb + n) = w;
                }
            }
        }
    }
}

// ---------------- flash attention (f32 math, bf16 hi/lo out) ---------------
#define AT_PAD 132
#define ATT_SMEM ((3 * 64 * AT_PAD + 64 * 65) * (int)sizeof(float))

__global__ __launch_bounds__(256) void attn_kernel(
    const float* __restrict__ q, int qstride,
    const float* __restrict__ k, int kstride, int koff,
    const float* __restrict__ v, int vstride, int voff,
    bf16* __restrict__ ohi, bf16* __restrict__ olo,
    int S, int Skv, float scale)
{
    extern __shared__ float smp[];
    float* qsm = smp;
    float* ksm = qsm + 64 * AT_PAD;
    float* vsm = ksm + 64 * AT_PAD;
    float* sc  = vsm + 64 * AT_PAD;

    int s0 = blockIdx.x * 64;
    int h  = blockIdx.y;
    int b  = blockIdx.z;
    int tid = threadIdx.x;

    for (int f = tid; f < 64 * 32; f += 256) {
        int r = f >> 5, d4 = f & 31;
        float4 qv = *(const float4*)(q + ((size_t)(b * S + s0 + r)) * qstride + h * HDD + d4 * 4);
        qv.x *= scale; qv.y *= scale; qv.z *= scale; qv.w *= scale;
        *(float4*)(qsm + r * AT_PAD + d4 * 4) = qv;
    }

    int qr = tid & 63;
    int quarter = tid >> 6;
    int c0 = quarter * 16;

    float o[32];
#pragma unroll
    for (int j = 0; j < 32; ++j) o[j] = 0.f;
    float m = -1e30f, l = 0.f;

    for (int kt = 0; kt < Skv; kt += 64) {
        __syncthreads();
        for (int f = tid; f < 64 * 32; f += 256) {
            int r = f >> 5, d4 = f & 31;
            size_t krow = (size_t)(b * Skv + kt + r);
            float4 kvv = *(const float4*)(k + krow * kstride + koff + h * HDD + d4 * 4);
            *(float4*)(ksm + r * AT_PAD + d4 * 4) = kvv;
            float4 vvv = *(const float4*)(v + krow * vstride + voff + h * HDD + d4 * 4);
            *(float4*)(vsm + r * AT_PAD + d4 * 4) = vvv;
        }
        __syncthreads();

        float accs[16];
#pragma unroll
        for (int c = 0; c < 16; ++c) accs[c] = 0.f;
        for (int d4 = 0; d4 < 32; ++d4) {
            float4 qv = *(const float4*)(qsm + qr * AT_PAD + d4 * 4);
#pragma unroll
            for (int c = 0; c < 16; ++c) {
                float4 kv4 = *(const float4*)(ksm + (c0 + c) * AT_PAD + d4 * 4);
                accs[c] += qv.x * kv4.x + qv.y * kv4.y + qv.z * kv4.z + qv.w * kv4.w;
            }
        }
#pragma unroll
        for (int c = 0; c < 16; ++c) sc[qr * 65 + c0 + c] = accs[c];
        __syncthreads();

        float tmax = -1e30f;
        for (int c = 0; c < 64; ++c) tmax = fmaxf(tmax, sc[qr * 65 + c]);
        float mnew = fmaxf(m, tmax);
        float corr = __expf(m - mnew);
        l *= corr;
#pragma unroll
        for (int j = 0; j < 32; ++j) o[j] *= corr;
        for (int c = 0; c < 64; ++c) {
            float p = __expf(sc[qr * 65 + c] - mnew);
            l += p;
            const float* vr = vsm + c * AT_PAD + quarter * 32;
#pragma unroll
            for (int j4 = 0; j4 < 8; ++j4) {
                float4 vv = *(const float4*)(vr + j4 * 4);
                o[j4 * 4 + 0] += p * vv.x;
                o[j4 * 4 + 1] += p * vv.y;
                o[j4 * 4 + 2] += p * vv.z;
                o[j4 * 4 + 3] += p * vv.w;
            }
        }
        m = mnew;
    }

    float invl = 1.f / l;
    size_t ob = ((size_t)(b * S + s0 + qr)) * DIMC + h * HDD + quarter * 32;
#pragma unroll
    for (int j = 0; j < 32; j += 2) {
        float v0 = o[j] * invl, v1 = o[j + 1] * invl;
        bf16 h0 = __float2bfloat16(v0), h1 = __float2bfloat16(v1);
        bf162 hv; hv.x = h0; hv.y = h1;
        bf162 lv;
        lv.x = __float2bfloat16(v0 - __bfloat162float(h0));
        lv.y = __float2bfloat16(v1 - __bfloat162float(h1));
        *(bf162*)(ohi + ob + j) = hv;
        *(bf162*)(olo + ob + j) = lv;
    }
}

// ---------------- host orchestration ----------------
static void launch_gemm(const bf16* Ah, const bf16* Al, const bf16* Bh, const bf16* Bl,
                        const float* bias, float* C, bf16* Chi, bf16* Clo,
                        int M, int N, int K, int mode, const float* res,
                        const float* sst, const float* temb, int gidx, int rpb)
{
    dim3 grid(M / 128, N / 128);
    gemm_mma<<<grid, 256, GEMM_SMEM>>>(Ah, Al, Bh, Bl, bias, C, Chi, Clo,
                                       N, K, mode, res, sst, temb, gidx, rpb);
}

extern "C" void kernel_launch(void* const* d_in, const int* in_sizes, int n_in,
                              void* d_out, int out_size)
{
    const float* hs    = (const float*)d_in[0];
    const float* enc   = (const float*)d_in[1];
    const float* temb  = (const float*)d_in[2];
    const float* cosT  = (const float*)d_in[3];
    const float* sinT  = (const float*)d_in[4];
    const float* sst   = (const float*)d_in[5];
    const float* w_qkv = (const float*)d_in[6];
    const float* b_qkv = (const float*)d_in[7];
    const float* rms_q1= (const float*)d_in[8];
    const float* rms_k1= (const float*)d_in[9];
    const float* w_o1  = (const float*)d_in[10];
    const float* b_o1  = (const float*)d_in[11];
    const float* ln2_g = (const float*)d_in[12];
    const float* ln2_b = (const float*)d_in[13];
    const float* w_q2  = (const float*)d_in[14];
    const float* b_q2  = (const float*)d_in[15];
    const float* w_kv2 = (const float*)d_in[16];
    const float* b_kv2 = (const float*)d_in[17];
    const float* rms_q2= (const float*)d_in[18];
    const float* rms_k2= (const float*)d_in[19];
    const float* w_o2  = (const float*)d_in[20];
    const float* b_o2  = (const float*)d_in[21];
    const float* w_ff1 = (const float*)d_in[22];
    const float* b_ff1 = (const float*)d_in[23];
    const float* w_ff2 = (const float*)d_in[24];
    const float* b_ff2 = (const float*)d_in[25];
    float* out = (float*)d_out;

    float *pqkv, *pq, *pk, *ph, *pkv;
    bf16 *pxh, *pxl, *pah, *pal, *pfh, *pfl, *peh, *pel;
    bf16 *w0h,*w0l,*w1h,*w1l,*w2h,*w2l,*w3h,*w3l,*w4h,*w4l,*w5h,*w5l,*w6h,*w6l;
    cudaGetSymbolAddress((void**)&pqkv, g_qkv);
    cudaGetSymbolAddress((void**)&pq,   g_q);
    cudaGetSymbolAddress((void**)&pk,   g_k);
    cudaGetSymbolAddress((void**)&ph,   g_h);
    cudaGetSymbolAddress((void**)&pkv,  g_kv);
    cudaGetSymbolAddress((void**)&pxh,  g_xh);  cudaGetSymbolAddress((void**)&pxl, g_xl);
    cudaGetSymbolAddress((void**)&pah,  g_ah);  cudaGetSymbolAddress((void**)&pal, g_al);
    cudaGetSymbolAddress((void**)&pfh,  g_fh);  cudaGetSymbolAddress((void**)&pfl, g_fl);
    cudaGetSymbolAddress((void**)&peh,  g_eh);  cudaGetSymbolAddress((void**)&pel, g_el);
    cudaGetSymbolAddress((void**)&w0h, g_w0h);  cudaGetSymbolAddress((void**)&w0l, g_w0l);
    cudaGetSymbolAddress((void**)&w1h, g_w1h);  cudaGetSymbolAddress((void**)&w1l, g_w1l);
    cudaGetSymbolAddress((void**)&w2h, g_w2h);  cudaGetSymbolAddress((void**)&w2l, g_w2l);
    cudaGetSymbolAddress((void**)&w3h, g_w3h);  cudaGetSymbolAddress((void**)&w3l, g_w3l);
    cudaGetSymbolAddress((void**)&w4h, g_w4h);  cudaGetSymbolAddress((void**)&w4l, g_w4l);
    cudaGetSymbolAddress((void**)&w5h, g_w5h);  cudaGetSymbolAddress((void**)&w5l, g_w5l);
    cudaGetSymbolAddress((void**)&w6h, g_w6h);  cudaGetSymbolAddress((void**)&w6l, g_w6l);

    cudaFuncSetAttribute(gemm_mma, cudaFuncAttributeMaxDynamicSharedMemorySize, GEMM_SMEM);
    cudaFuncSetAttribute(attn_kernel, cudaFuncAttributeMaxDynamicSharedMemorySize, ATT_SMEM);

    const float scale = 0.08838834764831845f;  // 128^-0.5

    // weight / encoder splits
    split_kernel<<<2048, 256>>>(w_qkv, w0h, w0l, (size_t)3 * DIMC * DIMC);
    split_kernel<<<2048, 256>>>(w_o1,  w1h, w1l, (size_t)DIMC * DIMC);
    split_kernel<<<2048, 256>>>(w_q2,  w2h, w2l, (size_t)DIMC * DIMC);
    split_kernel<<<2048, 256>>>(w_kv2, w3h, w3l, (size_t)2 * DIMC * DIMC);
    split_kernel<<<2048, 256>>>(w_o2,  w4h, w4l, (size_t)DIMC * DIMC);
    split_kernel<<<2048, 256>>>(w_ff1, w5h, w5l, (size_t)FFNN * DIMC);
    split_kernel<<<2048, 256>>>(w_ff2, w6h, w6l, (size_t)DIMC * FFNN);
    split_kernel<<<1024, 256>>>(enc,   peh, pel, (size_t)ROWSC * DIMC);

    // 1) x = modLN(h; shift=0, scale=1) -> bf16 hi/lo
    ln_kernel<<<ROWS, 256>>>(hs, pxh, pxl, nullptr, nullptr, sst, temb, 0, 1, SS);
    // 2) qkv = x @ w_qkv^T + b  (f32 out)
    launch_gemm(pxh, pxl, w0h, w0l, b_qkv, pqkv, nullptr, nullptr,
                ROWS, 3 * DIMC, DIMC, 0, nullptr, nullptr, nullptr, 0, SS);
    // 3) q,k = rope(rms(.))
    rmsrope_kernel<<<ROWS, 256>>>(pqkv, 3 * DIMC, 0,    pq, rms_q1, cosT, sinT, SS);
    rmsrope_kernel<<<ROWS, 256>>>(pqkv, 3 * DIMC, DIMC, pk, rms_k1, cosT, sinT, SS);
    // 4) self-attention -> bf16 hi/lo
    attn_kernel<<<dim3(SS / 64, HH, BB), 256, ATT_SMEM>>>(
        pq, DIMC, pk, DIMC, 0, pqkv, 3 * DIMC, 2 * DIMC, pah, pal, SS, SS, scale);
    // 5) h = hidden + gate_sa * (attn @ w_o1^T + b_o1)
    launch_gemm(pah, pal, w1h, w1l, b_o1, ph, nullptr, nullptr,
                ROWS, DIMC, DIMC, 2, hs, sst, temb, 2, SS);
    // 6) x = LN(h, g, b)
    ln_kernel<<<ROWS, 256>>>(ph, pxh, pxl, ln2_g, ln2_b, nullptr, nullptr, 0, 0, SS);
    // 7) q2 = rms(x @ w_q2^T + b_q2)
    launch_gemm(pxh, pxl, w2h, w2l, b_q2, pq, nullptr, nullptr,
                ROWS, DIMC, DIMC, 0, nullptr, nullptr, nullptr, 0, SS);
    rms_kernel<<<ROWS, 256>>>(pq, DIMC, 0, rms_q2);
    // 8) kv = enc @ w_kv2^T + b ; rms k-half in place
    launch_gemm(peh, pel, w3h, w3l, b_kv2, pkv, nullptr, nullptr,
                ROWSC, 2 * DIMC, DIMC, 0, nullptr, nullptr, nullptr, 0, SCC);
    rms_kernel<<<ROWSC, 256>>>(pkv, 2 * DIMC, 0, rms_k2);
    // 9) cross-attention -> bf16 hi/lo
    attn_kernel<<<dim3(SS / 64, HH, BB), 256, ATT_SMEM>>>(
        pq, DIMC, pkv, 2 * DIMC, 0, pkv, 2 * DIMC, DIMC, pah, pal, SS, SCC, scale);
    // 10) h += attn @ w_o2^T + b_o2
    launch_gemm(pah, pal, w4h, w4l, b_o2, ph, nullptr, nullptr,
                ROWS, DIMC, DIMC, 1, ph, nullptr, nullptr, 0, SS);
    // 11) x = modLN(h; shift=3, scale=4)
    ln_kernel<<<ROWS, 256>>>(ph, pxh, pxl, nullptr, nullptr, sst, temb, 3, 4, SS);
    // 12) f = gelu(x @ w_ff1^T + b_ff1) -> bf16 hi/lo
    launch_gemm(pxh, pxl, w5h, w5l, b_ff1, nullptr, pfh, pfl,
                ROWS, FFNN, DIMC, 3, nullptr, nullptr, nullptr, 0, SS);
    // 13) out = h + gate_ff * (f @ w_ff2^T + b_ff2)
    launch_gemm(pfh, pfl, w6h, w6l, b_ff2, out, nullptr, nullptr,
                ROWS, DIMC, FFNN, 2, ph, sst, temb, 5, SS);
}